// round 1
// baseline (speedup 1.0000x reference)
#include <cuda_runtime.h>
#include <cstdint>

#define SEQ 2048
#define INF 1024
#define HID 2048
#define OUT 1024

// Scratch (device globals — allocation-free per harness rules)
__device__ float g_gx[3][(size_t)SEQ * HID];   // precomputed Wx@x_t + b, per gate
__device__ float g_h[HID];                     // current hidden state
__device__ float g_rh[HID];                    // r * h broadcast buffer
__device__ unsigned g_bar_count;               // grid barrier
__device__ unsigned g_bar_gen;

// ---------------------------------------------------------------------------
// Grid-wide barrier (sense-counting). All CTAs guaranteed co-resident
// (128 CTAs, 1 per SM max usage). gen is monotonic; works across replays.
// ---------------------------------------------------------------------------
__device__ __forceinline__ void grid_barrier() {
    __syncthreads();
    if (threadIdx.x == 0) {
        __threadfence();
        unsigned my_gen = *(volatile unsigned*)&g_bar_gen;  // read BEFORE arrive
        if (atomicAdd(&g_bar_count, 1u) == gridDim.x - 1) {
            g_bar_count = 0;
            __threadfence();
            atomicAdd(&g_bar_gen, 1u);
        } else {
            while (*(volatile unsigned*)&g_bar_gen == my_gen) { }
        }
        __threadfence();
    }
    __syncthreads();
}

// ---------------------------------------------------------------------------
// Generic 64x64x16 fp32 tiled GEMM body:
//   C[m, n] = sum_k A[m*lda + k] * B[n*ldb + k] + bias[n]
// 256 threads, 4x4 register micro-tile. M, N multiples of 64; K multiple of 16.
// ---------------------------------------------------------------------------
__device__ __forceinline__ void sgemm_body(
    const float* __restrict__ A, int lda,
    const float* __restrict__ B, int ldb,
    const float* __restrict__ bias,
    float* __restrict__ C, int ldc,
    int K, int bm, int bn)
{
    __shared__ float As[16][64];
    __shared__ float Bs[16][64];

    const int tid = threadIdx.x;
    const int tx = tid & 15;        // 0..15 -> n
    const int ty = tid >> 4;        // 0..15 -> m
    const int arow = tid >> 2;      // 0..63
    const int ak   = (tid & 3) * 4; // 0,4,8,12

    float acc[4][4];
#pragma unroll
    for (int i = 0; i < 4; ++i)
#pragma unroll
        for (int j = 0; j < 4; ++j) acc[i][j] = 0.f;

    const float* Aptr = A + (size_t)(bm + arow) * lda + ak;
    const float* Bptr = B + (size_t)(bn + arow) * ldb + ak;

    for (int k0 = 0; k0 < K; k0 += 16) {
        float4 av = *(const float4*)(Aptr + k0);
        float4 bv = *(const float4*)(Bptr + k0);
        __syncthreads();
        As[ak + 0][arow] = av.x; As[ak + 1][arow] = av.y;
        As[ak + 2][arow] = av.z; As[ak + 3][arow] = av.w;
        Bs[ak + 0][arow] = bv.x; Bs[ak + 1][arow] = bv.y;
        Bs[ak + 2][arow] = bv.z; Bs[ak + 3][arow] = bv.w;
        __syncthreads();
#pragma unroll
        for (int kk = 0; kk < 16; ++kk) {
            float4 a4 = *(const float4*)&As[kk][ty * 4];
            float4 b4 = *(const float4*)&Bs[kk][tx * 4];
            acc[0][0] = fmaf(a4.x, b4.x, acc[0][0]);
            acc[0][1] = fmaf(a4.x, b4.y, acc[0][1]);
            acc[0][2] = fmaf(a4.x, b4.z, acc[0][2]);
            acc[0][3] = fmaf(a4.x, b4.w, acc[0][3]);
            acc[1][0] = fmaf(a4.y, b4.x, acc[1][0]);
            acc[1][1] = fmaf(a4.y, b4.y, acc[1][1]);
            acc[1][2] = fmaf(a4.y, b4.z, acc[1][2]);
            acc[1][3] = fmaf(a4.y, b4.w, acc[1][3]);
            acc[2][0] = fmaf(a4.z, b4.x, acc[2][0]);
            acc[2][1] = fmaf(a4.z, b4.y, acc[2][1]);
            acc[2][2] = fmaf(a4.z, b4.z, acc[2][2]);
            acc[2][3] = fmaf(a4.z, b4.w, acc[2][3]);
            acc[3][0] = fmaf(a4.w, b4.x, acc[3][0]);
            acc[3][1] = fmaf(a4.w, b4.y, acc[3][1]);
            acc[3][2] = fmaf(a4.w, b4.z, acc[3][2]);
            acc[3][3] = fmaf(a4.w, b4.w, acc[3][3]);
        }
    }

    const int cn = bn + tx * 4;
    float4 bias4 = *(const float4*)(bias + cn);
#pragma unroll
    for (int i = 0; i < 4; ++i) {
        float4 o;
        o.x = acc[i][0] + bias4.x;
        o.y = acc[i][1] + bias4.y;
        o.z = acc[i][2] + bias4.z;
        o.w = acc[i][3] + bias4.w;
        *(float4*)(C + (size_t)(bm + ty * 4 + i) * ldc + cn) = o;
    }
}

// Gx_j[t, i] = sum_k X[t, k] * W_j[i, HID + k] + b_j[i]     (j = blockIdx.z)
__global__ void __launch_bounds__(256) gemm_gx(
    const float* __restrict__ X,
    const float* __restrict__ Wu, const float* __restrict__ Wr,
    const float* __restrict__ Wc,
    const float* __restrict__ bu, const float* __restrict__ br,
    const float* __restrict__ bc)
{
    const float* B;
    const float* bias;
    if (blockIdx.z == 0)      { B = Wu; bias = bu; }
    else if (blockIdx.z == 1) { B = Wr; bias = br; }
    else                      { B = Wc; bias = bc; }
    float* C = &g_gx[blockIdx.z][0];
    sgemm_body(X, INF, B + HID, HID + INF, bias, C, HID, INF,
               blockIdx.y * 64, blockIdx.x * 64);
}

// outputs[t, o] = sum_h W_y[o, h] * hidden[t, h] + b_y[o]
__global__ void __launch_bounds__(256) gemm_y(
    const float* __restrict__ Hbuf, const float* __restrict__ Wy,
    const float* __restrict__ by, float* __restrict__ Yout)
{
    sgemm_body(Hbuf, HID, Wy, HID, by, Yout, OUT, HID,
               blockIdx.y * 64, blockIdx.x * 64);
}

// ---------------------------------------------------------------------------
// Persistent recurrent kernel. 128 CTAs x 256 threads. Each CTA owns 16 rows.
// Phase 1: u, r for own rows (2 matvec-rows each, 8 lanes per dot) -> publish r*h
// Phase 2: cand for own rows (16 lanes per dot) -> h_new, publish h
// Two grid barriers per step.
// ---------------------------------------------------------------------------
__global__ void __launch_bounds__(256, 1) gru_rec(
    const float* __restrict__ Wu, const float* __restrict__ Wr,
    const float* __restrict__ Wc, float* __restrict__ hid_out)
{
    __shared__ float sh_h[HID];
    __shared__ float sh_rh[HID];
    __shared__ float s_u[16];

    const int cta = blockIdx.x;      // 0..127
    const int tid = threadIdx.x;     // 0..255

    // h0 = 0
    for (int i = tid; i < HID; i += 256) sh_h[i] = 0.f;

    // Phase-1 mapping: 32 dot-slots (16 u-rows + 16 r-rows), 8 lanes each
    const int slot  = tid >> 3;             // 0..31
    const int lane8 = tid & 7;
    const int rowA  = (cta << 4) + (slot & 15);
    const bool isU  = (slot < 16);
    const float4* w1 = (const float4*)((isU ? Wu : Wr) + (size_t)rowA * (HID + INF));

    // Phase-2 mapping: 16 dot-slots, 16 lanes each
    const int grp    = tid >> 4;            // 0..15
    const int lane16 = tid & 15;
    const int rowC   = (cta << 4) + grp;
    const float4* wc = (const float4*)(Wc + (size_t)rowC * (HID + INF));

    const float* __restrict__ gxu = &g_gx[0][0];
    const float* __restrict__ gxr = &g_gx[1][0];
    const float* __restrict__ gxc = &g_gx[2][0];

    __syncthreads();

    for (int t = 0; t < SEQ; ++t) {
        // ---- Phase 1: u, r ----
        float sum = 0.f;
        const float4* h4 = (const float4*)sh_h;
#pragma unroll 8
        for (int k = lane8; k < HID / 4; k += 8) {
            float4 w = w1[k];
            float4 h = h4[k];
            sum = fmaf(w.x, h.x, sum);
            sum = fmaf(w.y, h.y, sum);
            sum = fmaf(w.z, h.z, sum);
            sum = fmaf(w.w, h.w, sum);
        }
        sum += __shfl_down_sync(0xffffffffu, sum, 4, 8);
        sum += __shfl_down_sync(0xffffffffu, sum, 2, 8);
        sum += __shfl_down_sync(0xffffffffu, sum, 1, 8);
        if (lane8 == 0) {
            if (isU) {
                float pre = sum + gxu[(size_t)t * HID + rowA];
                s_u[slot] = 1.f / (1.f + expf(-pre));
            } else {
                float pre = sum + gxr[(size_t)t * HID + rowA];
                float r = 1.f / (1.f + expf(-pre));
                g_rh[rowA] = r * sh_h[rowA];
            }
        }

        grid_barrier();

        // Broadcast r*h into shared
        for (int i = tid; i < HID / 4; i += 256)
            ((float4*)sh_rh)[i] = __ldcg(((const float4*)g_rh) + i);
        __syncthreads();

        // ---- Phase 2: candidate + h update ----
        float sc = 0.f;
        const float4* rh4 = (const float4*)sh_rh;
#pragma unroll 8
        for (int k = lane16; k < HID / 4; k += 16) {
            float4 w = wc[k];
            float4 v = rh4[k];
            sc = fmaf(w.x, v.x, sc);
            sc = fmaf(w.y, v.y, sc);
            sc = fmaf(w.z, v.z, sc);
            sc = fmaf(w.w, v.w, sc);
        }
        sc += __shfl_down_sync(0xffffffffu, sc, 8, 16);
        sc += __shfl_down_sync(0xffffffffu, sc, 4, 16);
        sc += __shfl_down_sync(0xffffffffu, sc, 2, 16);
        sc += __shfl_down_sync(0xffffffffu, sc, 1, 16);
        if (lane16 == 0) {
            float cand = tanhf(sc + gxc[(size_t)t * HID + rowC]);
            float u  = s_u[grp];
            float hp = sh_h[rowC];
            float hn = fmaf(u, cand - hp, hp);   // u*cand + (1-u)*hp
            g_h[rowC] = hn;
            hid_out[(size_t)t * HID + rowC] = hn;
        }

        grid_barrier();

        // Refresh full h into shared for next step
        for (int i = tid; i < HID / 4; i += 256)
            ((float4*)sh_h)[i] = __ldcg(((const float4*)g_h) + i);
        __syncthreads();
    }
}

// ---------------------------------------------------------------------------
extern "C" void kernel_launch(void* const* d_in, const int* in_sizes, int n_in,
                              void* d_out, int out_size)
{
    const float* X  = (const float*)d_in[0];
    const float* Wu = (const float*)d_in[1];
    const float* bu = (const float*)d_in[2];
    const float* Wr = (const float*)d_in[3];
    const float* br = (const float*)d_in[4];
    const float* Wc = (const float*)d_in[5];
    const float* bc = (const float*)d_in[6];
    const float* Wy = (const float*)d_in[7];
    const float* by = (const float*)d_in[8];

    float* outputs = (float*)d_out;                       // (SEQ, OUT)
    float* hidden  = (float*)d_out + (size_t)SEQ * OUT;   // (SEQ, HID)

    // 1) Gx_j = X @ Wx_j^T + b_j   (j = u, r, c)
    dim3 g1(HID / 64, SEQ / 64, 3);
    gemm_gx<<<g1, 256>>>(X, Wu, Wr, Wc, bu, br, bc);

    // 2) Sequential recurrence (persistent kernel, grid barriers)
    gru_rec<<<128, 256>>>(Wu, Wr, Wc, hidden);

    // 3) outputs = hidden @ W_y^T + b_y
    dim3 g2(OUT / 64, SEQ / 64);
    gemm_y<<<g2, 256>>>(hidden, Wy, by, outputs);
}

// round 2
// speedup vs baseline: 1.0245x; 1.0245x over previous
#include <cuda_runtime.h>
#include <cuda_fp16.h>
#include <cstdint>

#define SEQ 2048
#define INF 1024
#define HID 2048
#define OUT 1024

// Scratch (device globals — allocation-free per harness rules)
__device__ float g_gx[3][(size_t)SEQ * HID];   // precomputed Wx@x_t + b, per gate
__device__ float g_h[HID];                     // current hidden state
__device__ float g_rh[HID];                    // r * h broadcast buffer
__device__ unsigned g_bar_count;               // grid barrier
__device__ unsigned g_bar_gen;

// ---------------------------------------------------------------------------
// Grid-wide barrier (sense-counting). All CTAs co-resident (128 CTAs, 1/SM).
// ---------------------------------------------------------------------------
__device__ __forceinline__ void grid_barrier() {
    __syncthreads();
    if (threadIdx.x == 0) {
        __threadfence();
        unsigned my_gen = *(volatile unsigned*)&g_bar_gen;  // read BEFORE arrive
        if (atomicAdd(&g_bar_count, 1u) == gridDim.x - 1) {
            g_bar_count = 0;
            __threadfence();
            atomicAdd(&g_bar_gen, 1u);
        } else {
            while (*(volatile unsigned*)&g_bar_gen == my_gen) { }
        }
        __threadfence();
    }
    __syncthreads();
}

// ---------------------------------------------------------------------------
// Generic 64x64x16 fp32 tiled GEMM body:
//   C[m, n] = sum_k A[m*lda + k] * B[n*ldb + k] + bias[n]
// ---------------------------------------------------------------------------
__device__ __forceinline__ void sgemm_body(
    const float* __restrict__ A, int lda,
    const float* __restrict__ B, int ldb,
    const float* __restrict__ bias,
    float* __restrict__ C, int ldc,
    int K, int bm, int bn)
{
    __shared__ float As[16][64];
    __shared__ float Bs[16][64];

    const int tid = threadIdx.x;
    const int tx = tid & 15;
    const int ty = tid >> 4;
    const int arow = tid >> 2;
    const int ak   = (tid & 3) * 4;

    float acc[4][4];
#pragma unroll
    for (int i = 0; i < 4; ++i)
#pragma unroll
        for (int j = 0; j < 4; ++j) acc[i][j] = 0.f;

    const float* Aptr = A + (size_t)(bm + arow) * lda + ak;
    const float* Bptr = B + (size_t)(bn + arow) * ldb + ak;

    for (int k0 = 0; k0 < K; k0 += 16) {
        float4 av = *(const float4*)(Aptr + k0);
        float4 bv = *(const float4*)(Bptr + k0);
        __syncthreads();
        As[ak + 0][arow] = av.x; As[ak + 1][arow] = av.y;
        As[ak + 2][arow] = av.z; As[ak + 3][arow] = av.w;
        Bs[ak + 0][arow] = bv.x; Bs[ak + 1][arow] = bv.y;
        Bs[ak + 2][arow] = bv.z; Bs[ak + 3][arow] = bv.w;
        __syncthreads();
#pragma unroll
        for (int kk = 0; kk < 16; ++kk) {
            float4 a4 = *(const float4*)&As[kk][ty * 4];
            float4 b4 = *(const float4*)&Bs[kk][tx * 4];
            acc[0][0] = fmaf(a4.x, b4.x, acc[0][0]);
            acc[0][1] = fmaf(a4.x, b4.y, acc[0][1]);
            acc[0][2] = fmaf(a4.x, b4.z, acc[0][2]);
            acc[0][3] = fmaf(a4.x, b4.w, acc[0][3]);
            acc[1][0] = fmaf(a4.y, b4.x, acc[1][0]);
            acc[1][1] = fmaf(a4.y, b4.y, acc[1][1]);
            acc[1][2] = fmaf(a4.y, b4.z, acc[1][2]);
            acc[1][3] = fmaf(a4.y, b4.w, acc[1][3]);
            acc[2][0] = fmaf(a4.z, b4.x, acc[2][0]);
            acc[2][1] = fmaf(a4.z, b4.y, acc[2][1]);
            acc[2][2] = fmaf(a4.z, b4.z, acc[2][2]);
            acc[2][3] = fmaf(a4.z, b4.w, acc[2][3]);
            acc[3][0] = fmaf(a4.w, b4.x, acc[3][0]);
            acc[3][1] = fmaf(a4.w, b4.y, acc[3][1]);
            acc[3][2] = fmaf(a4.w, b4.z, acc[3][2]);
            acc[3][3] = fmaf(a4.w, b4.w, acc[3][3]);
        }
    }

    const int cn = bn + tx * 4;
    float4 bias4 = *(const float4*)(bias + cn);
#pragma unroll
    for (int i = 0; i < 4; ++i) {
        float4 o;
        o.x = acc[i][0] + bias4.x;
        o.y = acc[i][1] + bias4.y;
        o.z = acc[i][2] + bias4.z;
        o.w = acc[i][3] + bias4.w;
        *(float4*)(C + (size_t)(bm + ty * 4 + i) * ldc + cn) = o;
    }
}

__global__ void __launch_bounds__(256) gemm_gx(
    const float* __restrict__ X,
    const float* __restrict__ Wu, const float* __restrict__ Wr,
    const float* __restrict__ Wc,
    const float* __restrict__ bu, const float* __restrict__ br,
    const float* __restrict__ bc)
{
    const float* B;
    const float* bias;
    if (blockIdx.z == 0)      { B = Wu; bias = bu; }
    else if (blockIdx.z == 1) { B = Wr; bias = br; }
    else                      { B = Wc; bias = bc; }
    float* C = &g_gx[blockIdx.z][0];
    sgemm_body(X, INF, B + HID, HID + INF, bias, C, HID, INF,
               blockIdx.y * 64, blockIdx.x * 64);
}

__global__ void __launch_bounds__(256) gemm_y(
    const float* __restrict__ Hbuf, const float* __restrict__ Wy,
    const float* __restrict__ by, float* __restrict__ Yout)
{
    sgemm_body(Hbuf, HID, Wy, HID, by, Yout, OUT, HID,
               blockIdx.y * 64, blockIdx.x * 64);
}

// ---------------------------------------------------------------------------
// Persistent recurrent kernel. 128 CTAs x 512 threads, 1 CTA/SM.
// All recurrent weights held in SMEM as fp16 (192 KB/CTA), converted once.
//   Phase 1: u, r rows (32 slots x 16 lanes), publish r*h
//   Phase 2: cand rows (16 rows x 32 lanes), h update, publish h
// ---------------------------------------------------------------------------
#define REC_THREADS 512
// SMEM: 3 * 16 * 2048 halves (196608 B) + sh_h (8192) + sh_rh (8192) + s_u (64)
#define REC_SMEM (3 * 16 * 2048 * 2 + 2048 * 4 * 2 + 64)

__global__ void __launch_bounds__(REC_THREADS, 1) gru_rec(
    const float* __restrict__ Wu, const float* __restrict__ Wr,
    const float* __restrict__ Wc, float* __restrict__ hid_out)
{
    extern __shared__ unsigned char smem_raw[];
    __half* w_u = (__half*)smem_raw;             // [16][2048]
    __half* w_r = w_u + 16 * 2048;
    __half* w_c = w_r + 16 * 2048;
    float* sh_h  = (float*)(w_c + 16 * 2048);    // [2048]
    float* sh_rh = sh_h + 2048;                  // [2048]
    float* s_u   = sh_rh + 2048;                 // [16]

    const int cta = blockIdx.x;      // 0..127
    const int tid = threadIdx.x;     // 0..511

    // ---- Prologue: convert this CTA's weight rows to fp16 in SMEM ----
    {
        const float* src[3] = {Wu, Wr, Wc};
        __half* dst[3] = {w_u, w_r, w_c};
#pragma unroll
        for (int g = 0; g < 3; ++g) {
            const float* s = src[g];
            __half* d = dst[g];
            for (int i = tid; i < 16 * (HID / 4); i += REC_THREADS) {
                int row  = i >> 9;          // /512
                int col4 = i & 511;
                float4 v = *(const float4*)(s + (size_t)(cta * 16 + row) * (HID + INF) + col4 * 4);
                __half2 p0 = __floats2half2_rn(v.x, v.y);
                __half2 p1 = __floats2half2_rn(v.z, v.w);
                *(__half2*)(d + row * 2048 + col4 * 4)     = p0;
                *(__half2*)(d + row * 2048 + col4 * 4 + 2) = p1;
            }
        }
    }

    // h0 = 0
    {
        float4 z = make_float4(0.f, 0.f, 0.f, 0.f);
        ((float4*)sh_h)[tid] = z;   // 512 float4 == 2048 floats
    }
    __syncthreads();

    // Phase-1 mapping: 32 slots (16 u + 16 r) x 16 lanes
    const int slot   = tid >> 4;
    const int lane16 = tid & 15;
    const int lrow   = slot & 15;
    const int rowA   = (cta << 4) + lrow;
    const bool isU   = (slot < 16);
    const uint4* wp1 = (const uint4*)((isU ? w_u : w_r) + lrow * 2048);
    const float* gx1 = isU ? &g_gx[0][0] : &g_gx[1][0];

    // Phase-2 mapping: 16 rows x 32 lanes (one warp per row)
    const int grp  = tid >> 5;
    const int l32  = tid & 31;
    const int rowC = (cta << 4) + grp;
    const uint4* wp2 = (const uint4*)(w_c + grp * 2048);
    const float* gxc = &g_gx[2][0];

    for (int t = 0; t < SEQ; ++t) {
        // ---- Phase 1: u, r ----
        float gxv = __ldcg(&gx1[(size_t)t * HID + rowA]);   // prefetch early
        float a0 = 0.f, a1 = 0.f, a2 = 0.f, a3 = 0.f;
        float a4 = 0.f, a5 = 0.f, a6 = 0.f, a7 = 0.f;
        const float4* hp = (const float4*)sh_h;
#pragma unroll
        for (int it = 0; it < 16; ++it) {
            int k = lane16 + (it << 4);          // 0..255 (uint4 index)
            uint4 wv = wp1[k];
            float4 ha = hp[2 * k];
            float4 hb = hp[2 * k + 1];
            float2 f0 = __half22float2(*reinterpret_cast<__half2*>(&wv.x));
            float2 f1 = __half22float2(*reinterpret_cast<__half2*>(&wv.y));
            float2 f2 = __half22float2(*reinterpret_cast<__half2*>(&wv.z));
            float2 f3 = __half22float2(*reinterpret_cast<__half2*>(&wv.w));
            a0 = fmaf(f0.x, ha.x, a0);
            a1 = fmaf(f0.y, ha.y, a1);
            a2 = fmaf(f1.x, ha.z, a2);
            a3 = fmaf(f1.y, ha.w, a3);
            a4 = fmaf(f2.x, hb.x, a4);
            a5 = fmaf(f2.y, hb.y, a5);
            a6 = fmaf(f3.x, hb.z, a6);
            a7 = fmaf(f3.y, hb.w, a7);
        }
        float sum = ((a0 + a1) + (a2 + a3)) + ((a4 + a5) + (a6 + a7));
        sum += __shfl_down_sync(0xffffffffu, sum, 8, 16);
        sum += __shfl_down_sync(0xffffffffu, sum, 4, 16);
        sum += __shfl_down_sync(0xffffffffu, sum, 2, 16);
        sum += __shfl_down_sync(0xffffffffu, sum, 1, 16);
        if (lane16 == 0) {
            float pre = sum + gxv;
            float sg = 1.f / (1.f + expf(-pre));
            if (isU) {
                s_u[lrow] = sg;
            } else {
                g_rh[rowA] = sg * sh_h[rowA];
            }
        }

        grid_barrier();

        // Broadcast r*h into shared (512 threads x 1 float4)
        ((float4*)sh_rh)[tid] = __ldcg(((const float4*)g_rh) + tid);
        __syncthreads();

        // ---- Phase 2: candidate + h update ----
        float gxcv = __ldcg(&gxc[(size_t)t * HID + rowC]);
        float c0 = 0.f, c1 = 0.f, c2 = 0.f, c3 = 0.f;
        float c4 = 0.f, c5 = 0.f, c6 = 0.f, c7 = 0.f;
        const float4* rp = (const float4*)sh_rh;
#pragma unroll
        for (int it = 0; it < 8; ++it) {
            int k = l32 + (it << 5);             // 0..255
            uint4 wv = wp2[k];
            float4 ha = rp[2 * k];
            float4 hb = rp[2 * k + 1];
            float2 f0 = __half22float2(*reinterpret_cast<__half2*>(&wv.x));
            float2 f1 = __half22float2(*reinterpret_cast<__half2*>(&wv.y));
            float2 f2 = __half22float2(*reinterpret_cast<__half2*>(&wv.z));
            float2 f3 = __half22float2(*reinterpret_cast<__half2*>(&wv.w));
            c0 = fmaf(f0.x, ha.x, c0);
            c1 = fmaf(f0.y, ha.y, c1);
            c2 = fmaf(f1.x, ha.z, c2);
            c3 = fmaf(f1.y, ha.w, c3);
            c4 = fmaf(f2.x, hb.x, c4);
            c5 = fmaf(f2.y, hb.y, c5);
            c6 = fmaf(f3.x, hb.z, c6);
            c7 = fmaf(f3.y, hb.w, c7);
        }
        float sc = ((c0 + c1) + (c2 + c3)) + ((c4 + c5) + (c6 + c7));
        sc += __shfl_down_sync(0xffffffffu, sc, 16);
        sc += __shfl_down_sync(0xffffffffu, sc, 8);
        sc += __shfl_down_sync(0xffffffffu, sc, 4);
        sc += __shfl_down_sync(0xffffffffu, sc, 2);
        sc += __shfl_down_sync(0xffffffffu, sc, 1);
        if (l32 == 0) {
            float cand = tanhf(sc + gxcv);
            float u  = s_u[grp];
            float hprev = sh_h[rowC];
            float hn = fmaf(u, cand - hprev, hprev);   // u*cand + (1-u)*h
            g_h[rowC] = hn;
            hid_out[(size_t)t * HID + rowC] = hn;
        }

        grid_barrier();

        // Refresh full h into shared for next step
        ((float4*)sh_h)[tid] = __ldcg(((const float4*)g_h) + tid);
        __syncthreads();
    }
}

// ---------------------------------------------------------------------------
extern "C" void kernel_launch(void* const* d_in, const int* in_sizes, int n_in,
                              void* d_out, int out_size)
{
    const float* X  = (const float*)d_in[0];
    const float* Wu = (const float*)d_in[1];
    const float* bu = (const float*)d_in[2];
    const float* Wr = (const float*)d_in[3];
    const float* br = (const float*)d_in[4];
    const float* Wc = (const float*)d_in[5];
    const float* bc = (const float*)d_in[6];
    const float* Wy = (const float*)d_in[7];
    const float* by = (const float*)d_in[8];

    float* outputs = (float*)d_out;                       // (SEQ, OUT)
    float* hidden  = (float*)d_out + (size_t)SEQ * OUT;   // (SEQ, HID)

    static bool attr_set = false;
    if (!attr_set) {
        cudaFuncSetAttribute(gru_rec, cudaFuncAttributeMaxDynamicSharedMemorySize,
                             REC_SMEM);
        attr_set = true;
    }

    // 1) Gx_j = X @ Wx_j^T + b_j   (j = u, r, c)
    dim3 g1(HID / 64, SEQ / 64, 3);
    gemm_gx<<<g1, 256>>>(X, Wu, Wr, Wc, bu, br, bc);

    // 2) Sequential recurrence (persistent kernel, fp16 weights in SMEM)
    gru_rec<<<128, REC_THREADS, REC_SMEM>>>(Wu, Wr, Wc, hidden);

    // 3) outputs = hidden @ W_y^T + b_y
    dim3 g2(OUT / 64, SEQ / 64);
    gemm_y<<<g2, 256>>>(hidden, Wy, by, outputs);
}